// round 2
// baseline (speedup 1.0000x reference)
#include <cuda_runtime.h>
#include <cuda_bf16.h>

#define LATDIM 128
#define HEADS 4
#define MAXN 100000
#define MAXE 600000
#define SCAN_THREADS 1024

// Scratch (allocation-free: device globals)
__device__ float g_Q[(size_t)MAXN * LATDIM];
__device__ float g_K[(size_t)MAXN * LATDIM];
__device__ float g_V[(size_t)MAXN * LATDIM];
__device__ int   g_count[MAXN];
__device__ int   g_offset[MAXN + 1];
__device__ int   g_cursor[MAXN];
__device__ int   g_edgeIdx[MAXE];

// ---------------- packed fp32x2 helpers (Blackwell) ----------------
__device__ __forceinline__ unsigned long long pack2(float x, float y) {
    unsigned long long r;
    asm("mov.b64 %0, {%1, %2};" : "=l"(r) : "f"(x), "f"(y));
    return r;
}
__device__ __forceinline__ void fma2(unsigned long long& d,
                                     unsigned long long a,
                                     unsigned long long b) {
    asm("fma.rn.f32x2 %0, %1, %2, %0;" : "+l"(d) : "l"(a), "l"(b));
}

// ---------------- CSR build ----------------
__global__ void zero_counts(int N) {
    int i = blockIdx.x * blockDim.x + threadIdx.x;
    if (i < N) g_count[i] = 0;
}

__global__ void count_rows(const int* __restrict__ rows, int E) {
    int e = blockIdx.x * blockDim.x + threadIdx.x;
    if (e < E) atomicAdd(&g_count[rows[e]], 1);
}

// Single-block exclusive scan of g_count -> g_offset / g_cursor
__global__ void __launch_bounds__(SCAN_THREADS)
scan_counts(int N) {
    __shared__ int sums[SCAN_THREADS];
    int tid = threadIdx.x;
    int chunk = (N + SCAN_THREADS - 1) / SCAN_THREADS;
    int beg = tid * chunk;
    int end = min(beg + chunk, N);
    int s = 0;
    for (int i = beg; i < end; ++i) s += g_count[i];
    sums[tid] = s;
    __syncthreads();
    // Hillis-Steele inclusive scan
    for (int off = 1; off < SCAN_THREADS; off <<= 1) {
        int t = (tid >= off) ? sums[tid - off] : 0;
        __syncthreads();
        sums[tid] += t;
        __syncthreads();
    }
    int run = sums[tid] - s;   // exclusive prefix for this thread's chunk
    for (int i = beg; i < end; ++i) {
        int c = g_count[i];
        g_offset[i] = run;
        g_cursor[i] = run;
        run += c;
    }
    if (tid == SCAN_THREADS - 1) g_offset[N] = run;
}

__global__ void fill_csr(const int* __restrict__ rows, int E) {
    int e = blockIdx.x * blockDim.x + threadIdx.x;
    if (e < E) {
        int pos = atomicAdd(&g_cursor[rows[e]], 1);
        g_edgeIdx[pos] = e;
    }
}

// ---------------- QKV GEMM: [N,128] x [128,128] x3, fp32 via f32x2 ----------------
#define AS_STRIDE 132
__global__ void __launch_bounds__(256, 1)
qkv_gemm(const float* __restrict__ embeds,
         const float* __restrict__ qT,
         const float* __restrict__ kT,
         const float* __restrict__ vT,
         int N) {
    extern __shared__ float smem[];
    float* As = smem;                       // 128 * 132 floats
    float* Ws = smem + 128 * AS_STRIDE;     // 128 * 128 floats

    const int tid = threadIdx.x;
    const int m0 = blockIdx.x * 128;

    for (int i = tid; i < 128 * 32; i += 256) {
        int m = i >> 5;
        int k4 = i & 31;
        float4 v = make_float4(0.f, 0.f, 0.f, 0.f);
        int gm = m0 + m;
        if (gm < N) v = ((const float4*)embeds)[(size_t)gm * 32 + k4];
        *(float4*)&As[m * AS_STRIDE + k4 * 4] = v;
    }

    const float* Wsrc[3] = {qT, kT, vT};

    const int ty = tid >> 4;       // 0..15
    const int tx = tid & 15;       // 0..15
    const int mrow = ty * 8;
    const int ncol = tx * 8;

    for (int w = 0; w < 3; ++w) {
        __syncthreads();
        const float* W = Wsrc[w];
        for (int i = tid; i < 128 * 32; i += 256) {
            ((float4*)Ws)[i] = ((const float4*)W)[i];
        }
        __syncthreads();

        unsigned long long acc[8][4];
#pragma unroll
        for (int i = 0; i < 8; ++i)
#pragma unroll
            for (int j = 0; j < 4; ++j) acc[i][j] = 0ull;

#pragma unroll 4
        for (int k = 0; k < 128; ++k) {
            float a[8];
#pragma unroll
            for (int i = 0; i < 8; ++i) a[i] = As[(mrow + i) * AS_STRIDE + k];
            float4 b0 = *(const float4*)&Ws[k * 128 + ncol];
            float4 b1 = *(const float4*)&Ws[k * 128 + ncol + 4];
            unsigned long long bp[4];
            bp[0] = pack2(b0.x, b0.y);
            bp[1] = pack2(b0.z, b0.w);
            bp[2] = pack2(b1.x, b1.y);
            bp[3] = pack2(b1.z, b1.w);
#pragma unroll
            for (int i = 0; i < 8; ++i) {
                unsigned long long ap = pack2(a[i], a[i]);
#pragma unroll
                for (int j = 0; j < 4; ++j) fma2(acc[i][j], ap, bp[j]);
            }
        }

        float* D = (w == 0) ? g_Q : (w == 1) ? g_K : g_V;
#pragma unroll
        for (int i = 0; i < 8; ++i) {
            int gm = m0 + mrow + i;
            if (gm < N) {
                float o[8];
#pragma unroll
                for (int j = 0; j < 4; ++j) {
                    float2 f = *(float2*)&acc[i][j];
                    o[2 * j] = f.x;
                    o[2 * j + 1] = f.y;
                }
                *(float4*)&D[(size_t)gm * 128 + ncol] = *(float4*)&o[0];
                *(float4*)&D[(size_t)gm * 128 + ncol + 4] = *(float4*)&o[4];
            }
        }
    }
}

// ---------------- Fused row kernel: attention + softmax + aggregation ----------------
// One warp per destination row. No atomics. Writes out directly (covers all rows).
__global__ void __launch_bounds__(256)
row_attention(const int* __restrict__ cols,
              const float* __restrict__ filt,
              float* __restrict__ out, int N) {
    int r = (blockIdx.x * blockDim.x + threadIdx.x) >> 5;
    int lane = threadIdx.x & 31;
    if (r >= N) return;
    int h = lane >> 3;   // head for this lane's 8-lane group

    int beg = g_offset[r];
    int end = g_offset[r + 1];

    float4 q = ((const float4*)g_Q)[(size_t)r * 32 + lane];

    float norm = 0.0f;   // per-head expAtt sum (replicated across 8 lanes of a group)
    float4 acc = make_float4(0.f, 0.f, 0.f, 0.f);

    for (int i = beg; i < end; ++i) {
        int e = __ldg(&g_edgeIdx[i]);
        int c = __ldg(&cols[e]);
        float4 k4 = ((const float4*)g_K)[(size_t)c * 32 + lane];
        float p = q.x * k4.x + q.y * k4.y + q.z * k4.z + q.w * k4.w;
        // reduce within 8-lane head group
        p += __shfl_xor_sync(0xffffffffu, p, 4);
        p += __shfl_xor_sync(0xffffffffu, p, 2);
        p += __shfl_xor_sync(0xffffffffu, p, 1);

        float att = fminf(fmaxf(p, -10.0f), 10.0f) + __ldg(&filt[(size_t)c * 4 + h]);
        float ea = expf(att);
        norm += ea;

        float4 v = ((const float4*)g_V)[(size_t)c * 32 + lane];
        acc.x = fmaf(ea, v.x, acc.x);
        acc.y = fmaf(ea, v.y, acc.y);
        acc.z = fmaf(ea, v.z, acc.z);
        acc.w = fmaf(ea, v.w, acc.w);
    }

    float inv = 1.0f / (norm + 1e-8f);
    acc.x *= inv; acc.y *= inv; acc.z *= inv; acc.w *= inv;
    ((float4*)out)[(size_t)r * 32 + lane] = acc;
}

// ---------------- launch ----------------
extern "C" void kernel_launch(void* const* d_in, const int* in_sizes, int n_in,
                              void* d_out, int out_size) {
    const float* embeds = (const float*)d_in[0];
    const float* qT = (const float*)d_in[1];
    const float* kT = (const float*)d_in[2];
    const float* vT = (const float*)d_in[3];
    const float* filt = (const float*)d_in[4];
    const int* rows = (const int*)d_in[5];
    const int* cols = (const int*)d_in[6];
    float* out = (float*)d_out;

    int N = in_sizes[0] / LATDIM;
    int E = in_sizes[5];

    static const int GEMM_SMEM = 128 * AS_STRIDE * 4 + 128 * 128 * 4;
    cudaFuncSetAttribute(qkv_gemm, cudaFuncAttributeMaxDynamicSharedMemorySize, GEMM_SMEM);

    // CSR build
    zero_counts<<<(N + 255) / 256, 256>>>(N);
    count_rows<<<(E + 255) / 256, 256>>>(rows, E);
    scan_counts<<<1, SCAN_THREADS>>>(N);
    fill_csr<<<(E + 255) / 256, 256>>>(rows, E);

    // Node-level QKV
    qkv_gemm<<<(N + 127) / 128, 256, GEMM_SMEM>>>(embeds, qT, kT, vT, N);

    // Fused attention (warp per row)
    row_attention<<<(N * 32 + 255) / 256, 256>>>(cols, filt, out, N);
}

// round 3
// speedup vs baseline: 1.2911x; 1.2911x over previous
#include <cuda_runtime.h>
#include <cuda_bf16.h>

#define LATDIM 128
#define HEADS 4
#define MAXN 100000
#define MAXE 600000

// Scratch (allocation-free: device globals)
__device__ float g_Q[(size_t)MAXN * LATDIM];
__device__ float g_K[(size_t)MAXN * LATDIM];
__device__ float g_V[(size_t)MAXN * LATDIM];
__device__ float g_expAtt[(size_t)MAXE * HEADS];
__device__ float g_attNorm[(size_t)MAXN * HEADS];

// ---------------- packed fp32x2 helpers (Blackwell) ----------------
__device__ __forceinline__ unsigned long long pack2(float x, float y) {
    unsigned long long r;
    asm("mov.b64 %0, {%1, %2};" : "=l"(r) : "f"(x), "f"(y));
    return r;
}
__device__ __forceinline__ void fma2(unsigned long long& d,
                                     unsigned long long a,
                                     unsigned long long b) {
    asm("fma.rn.f32x2 %0, %1, %2, %0;" : "+l"(d) : "l"(a), "l"(b));
}

// ---------------- zero out + attNorm ----------------
__global__ void zero_kernel(float* __restrict__ out, int n_out, int n_norm) {
    int stride = gridDim.x * blockDim.x;
    int i0 = blockIdx.x * blockDim.x + threadIdx.x;
    for (int i = i0; i < n_out; i += stride) out[i] = 0.0f;
    for (int i = i0; i < n_norm; i += stride) g_attNorm[i] = 0.0f;
}

// ---------------- QKV GEMM: [N,128] x [128,128] x3, fp32 via f32x2 ----------------
// A tile stored k-major (transposed) so row-pairs load as packed f32x2 directly.
// Block: 256 threads, M-tile = 128 rows. Each thread: 8 rows x 8 cols.
#define AST 132   // k-major row stride in floats (132*4 = 528 B, 16B aligned)
__global__ void __launch_bounds__(256, 1)
qkv_gemm(const float* __restrict__ embeds,
         const float* __restrict__ qT,
         const float* __restrict__ kT,
         const float* __restrict__ vT,
         int N) {
    extern __shared__ float smem[];
    float* AsT = smem;                      // [128 k][AST] (m contiguous)
    float* Ws  = smem + 128 * AST;          // [128 k][128 n]

    const int tid = threadIdx.x;
    const int m0 = blockIdx.x * 128;

    // Load A tile transposed: AsT[k][m] = embeds[m0+m][k]
    for (int i = tid; i < 128 * 32; i += 256) {
        int m = i >> 5;
        int k4 = i & 31;
        float4 v = make_float4(0.f, 0.f, 0.f, 0.f);
        int gm = m0 + m;
        if (gm < N) v = ((const float4*)embeds)[(size_t)gm * 32 + k4];
        AsT[(4 * k4 + 0) * AST + m] = v.x;
        AsT[(4 * k4 + 1) * AST + m] = v.y;
        AsT[(4 * k4 + 2) * AST + m] = v.z;
        AsT[(4 * k4 + 3) * AST + m] = v.w;
    }

    const float* Wsrc[3] = {qT, kT, vT};

    const int ty = tid >> 4;       // 0..15
    const int tx = tid & 15;       // 0..15
    const int mrow = ty * 8;
    const int ncol = tx * 8;

    for (int w = 0; w < 3; ++w) {
        __syncthreads();
        const float* W = Wsrc[w];
        for (int i = tid; i < 128 * 32; i += 256) {
            ((float4*)Ws)[i] = ((const float4*)W)[i];
        }
        __syncthreads();

        // acc[rowpair][col]: (row 2i, col j) in lo, (row 2i+1, col j) in hi
        unsigned long long acc[4][8];
#pragma unroll
        for (int i = 0; i < 4; ++i)
#pragma unroll
            for (int j = 0; j < 8; ++j) acc[i][j] = 0ull;

#pragma unroll 4
        for (int k = 0; k < 128; ++k) {
            // 4 packed row-pairs, loaded directly (no packing instructions)
            ulonglong2 a01 = *(const ulonglong2*)&AsT[k * AST + mrow];
            ulonglong2 a23 = *(const ulonglong2*)&AsT[k * AST + mrow + 4];
            unsigned long long ap[4] = {a01.x, a01.y, a23.x, a23.y};

            float4 b0 = *(const float4*)&Ws[k * 128 + ncol];
            float4 b1 = *(const float4*)&Ws[k * 128 + ncol + 4];
            unsigned long long bd[8];
            bd[0] = pack2(b0.x, b0.x); bd[1] = pack2(b0.y, b0.y);
            bd[2] = pack2(b0.z, b0.z); bd[3] = pack2(b0.w, b0.w);
            bd[4] = pack2(b1.x, b1.x); bd[5] = pack2(b1.y, b1.y);
            bd[6] = pack2(b1.z, b1.z); bd[7] = pack2(b1.w, b1.w);

#pragma unroll
            for (int i = 0; i < 4; ++i)
#pragma unroll
                for (int j = 0; j < 8; ++j) fma2(acc[i][j], ap[i], bd[j]);
        }

        // Store: each acc column j holds two consecutive rows
        float* D = (w == 0) ? g_Q : (w == 1) ? g_K : g_V;
#pragma unroll
        for (int i = 0; i < 4; ++i) {
            int gm = m0 + mrow + 2 * i;
            if (gm < N) {
                float lo[8], hi[8];
#pragma unroll
                for (int j = 0; j < 8; ++j) {
                    float2 f = *(float2*)&acc[i][j];
                    lo[j] = f.x;
                    hi[j] = f.y;
                }
                *(float4*)&D[(size_t)gm * 128 + ncol]     = *(float4*)&lo[0];
                *(float4*)&D[(size_t)gm * 128 + ncol + 4] = *(float4*)&lo[4];
                if (gm + 1 < N) {
                    *(float4*)&D[(size_t)(gm + 1) * 128 + ncol]     = *(float4*)&hi[0];
                    *(float4*)&D[(size_t)(gm + 1) * 128 + ncol + 4] = *(float4*)&hi[4];
                }
            }
        }
    }
}

// ---------------- Edge pass A: 2 edges per warp, interleaved loads ----------------
__global__ void __launch_bounds__(256)
edge_att(const int* __restrict__ rows, const int* __restrict__ cols,
         const float* __restrict__ filt, int E) {
    int w = (blockIdx.x * blockDim.x + threadIdx.x) >> 5;
    int lane = threadIdx.x & 31;
    int e0 = 2 * w;
    if (e0 >= E) return;
    bool has1 = (e0 + 1 < E);

    int r0 = __ldg(&rows[e0]);
    int c0 = __ldg(&cols[e0]);
    int r1 = has1 ? __ldg(&rows[e0 + 1]) : r0;
    int c1 = has1 ? __ldg(&cols[e0 + 1]) : c0;

    // 4 independent 16B gathers, issued back-to-back
    float4 q0 = ((const float4*)g_Q)[(size_t)r0 * 32 + lane];
    float4 k0 = ((const float4*)g_K)[(size_t)c0 * 32 + lane];
    float4 q1 = ((const float4*)g_Q)[(size_t)r1 * 32 + lane];
    float4 k1 = ((const float4*)g_K)[(size_t)c1 * 32 + lane];

    float p0 = q0.x * k0.x + q0.y * k0.y + q0.z * k0.z + q0.w * k0.w;
    float p1 = q1.x * k1.x + q1.y * k1.y + q1.z * k1.z + q1.w * k1.w;
#pragma unroll
    for (int off = 4; off >= 1; off >>= 1) {
        p0 += __shfl_xor_sync(0xffffffffu, p0, off);
        p1 += __shfl_xor_sync(0xffffffffu, p1, off);
    }

    if ((lane & 7) == 0) {
        int h = lane >> 3;
        float f0 = __ldg(&filt[(size_t)c0 * 4 + h]);
        float att0 = fminf(fmaxf(p0, -10.0f), 10.0f) + f0;
        float ea0 = expf(att0);
        g_expAtt[(size_t)e0 * 4 + h] = ea0;
        atomicAdd(&g_attNorm[(size_t)r0 * 4 + h], ea0);
        if (has1) {
            float f1 = __ldg(&filt[(size_t)c1 * 4 + h]);
            float att1 = fminf(fmaxf(p1, -10.0f), 10.0f) + f1;
            float ea1 = expf(att1);
            g_expAtt[(size_t)(e0 + 1) * 4 + h] = ea1;
            atomicAdd(&g_attNorm[(size_t)r1 * 4 + h], ea1);
        }
    }
}

// ---------------- Edge pass B: 2 edges per warp, weighted V scatter ----------------
__global__ void __launch_bounds__(256)
edge_agg(const int* __restrict__ rows, const int* __restrict__ cols,
         float* __restrict__ out, int E) {
    int w = (blockIdx.x * blockDim.x + threadIdx.x) >> 5;
    int lane = threadIdx.x & 31;
    int e0 = 2 * w;
    if (e0 >= E) return;
    bool has1 = (e0 + 1 < E);
    int h = lane >> 3;

    int r0 = __ldg(&rows[e0]);
    int c0 = __ldg(&cols[e0]);
    int r1 = has1 ? __ldg(&rows[e0 + 1]) : r0;
    int c1 = has1 ? __ldg(&cols[e0 + 1]) : c0;

    float ea0 = __ldg(&g_expAtt[(size_t)e0 * 4 + h]);
    float nm0 = __ldg(&g_attNorm[(size_t)r0 * 4 + h]);
    float ea1 = __ldg(&g_expAtt[(size_t)(e0 + (has1 ? 1 : 0)) * 4 + h]);
    float nm1 = __ldg(&g_attNorm[(size_t)r1 * 4 + h]);
    float4 v0 = ((const float4*)g_V)[(size_t)c0 * 32 + lane];
    float4 v1 = ((const float4*)g_V)[(size_t)c1 * 32 + lane];

    float w0 = ea0 / (nm0 + 1e-8f);
    v0.x *= w0; v0.y *= w0; v0.z *= w0; v0.w *= w0;
    float* dst0 = out + (size_t)r0 * 128 + lane * 4;
    asm volatile("red.global.add.v4.f32 [%0], {%1, %2, %3, %4};"
                 :: "l"(dst0), "f"(v0.x), "f"(v0.y), "f"(v0.z), "f"(v0.w)
                 : "memory");

    if (has1) {
        float w1 = ea1 / (nm1 + 1e-8f);
        v1.x *= w1; v1.y *= w1; v1.z *= w1; v1.w *= w1;
        float* dst1 = out + (size_t)r1 * 128 + lane * 4;
        asm volatile("red.global.add.v4.f32 [%0], {%1, %2, %3, %4};"
                     :: "l"(dst1), "f"(v1.x), "f"(v1.y), "f"(v1.z), "f"(v1.w)
                     : "memory");
    }
}

// ---------------- launch ----------------
extern "C" void kernel_launch(void* const* d_in, const int* in_sizes, int n_in,
                              void* d_out, int out_size) {
    const float* embeds = (const float*)d_in[0];
    const float* qT = (const float*)d_in[1];
    const float* kT = (const float*)d_in[2];
    const float* vT = (const float*)d_in[3];
    const float* filt = (const float*)d_in[4];
    const int* rows = (const int*)d_in[5];
    const int* cols = (const int*)d_in[6];
    float* out = (float*)d_out;

    int N = in_sizes[0] / LATDIM;
    int E = in_sizes[5];

    static const int GEMM_SMEM = 128 * AST * 4 + 128 * 128 * 4;
    cudaFuncSetAttribute(qkv_gemm, cudaFuncAttributeMaxDynamicSharedMemorySize, GEMM_SMEM);

    zero_kernel<<<512, 256>>>(out, N * LATDIM, N * HEADS);
    qkv_gemm<<<(N + 127) / 128, 256, GEMM_SMEM>>>(embeds, qT, kT, vT, N);

    int nWarps = (E + 1) / 2;
    int blocksE = (nWarps * 32 + 255) / 256;
    edge_att<<<blocksE, 256>>>(rows, cols, filt, E);
    edge_agg<<<blocksE, 256>>>(rows, cols, out, E);
}

// round 5
// speedup vs baseline: 1.3222x; 1.0241x over previous
#include <cuda_runtime.h>
#include <cuda_bf16.h>
#include <cstdint>

#define LATDIM 128
#define HEADS 4
#define MAXN 100000
#define MAXE 600000

// Scratch (allocation-free: device globals)
__device__ float g_Q[(size_t)MAXN * LATDIM];
__device__ float g_K[(size_t)MAXN * LATDIM];
__device__ float g_V[(size_t)MAXN * LATDIM];
__device__ float g_expAtt[(size_t)MAXE * HEADS];
__device__ float g_attNorm[(size_t)MAXN * HEADS];

// ---------------- zero out + attNorm ----------------
__global__ void zero_kernel(float* __restrict__ out, int n_out, int n_norm) {
    int stride = gridDim.x * blockDim.x;
    int i0 = blockIdx.x * blockDim.x + threadIdx.x;
    for (int i = i0; i < n_out; i += stride) out[i] = 0.0f;
    for (int i = i0; i < n_norm; i += stride) g_attNorm[i] = 0.0f;
}

// ---------------- bf16 split helpers ----------------
// pair for (x0,x1) along k: .x = packed hi bf16x2, .y = packed lo bf16x2
__device__ __forceinline__ uint2 split2(float x0, float x1) {
    __nv_bfloat16 h0 = __float2bfloat16(x0);
    __nv_bfloat16 h1 = __float2bfloat16(x1);
    __nv_bfloat16 l0 = __float2bfloat16(x0 - __bfloat162float(h0));
    __nv_bfloat16 l1 = __float2bfloat16(x1 - __bfloat162float(h1));
    __nv_bfloat162 hh = __nv_bfloat162(h0, h1);   // h0 in low 16 bits
    __nv_bfloat162 ll = __nv_bfloat162(l0, l1);
    uint2 r;
    r.x = *reinterpret_cast<uint32_t*>(&hh);
    r.y = *reinterpret_cast<uint32_t*>(&ll);
    return r;
}

__device__ __forceinline__ void mma_bf16(float* d, const uint32_t* a,
                                         uint32_t b0, uint32_t b1) {
    asm volatile(
        "mma.sync.aligned.m16n8k16.row.col.f32.bf16.bf16.f32 "
        "{%0,%1,%2,%3}, {%4,%5,%6,%7}, {%8,%9}, {%0,%1,%2,%3};"
        : "+f"(d[0]), "+f"(d[1]), "+f"(d[2]), "+f"(d[3])
        : "r"(a[0]), "r"(a[1]), "r"(a[2]), "r"(a[3]), "r"(b0), "r"(b1));
}

// ---------------- QKV GEMM on tensor cores (mma.sync bf16, 3-term split) ----------------
// CTA: 256 threads = 8 warps (4 M x 2 N). CTA tile 128(M) x 128(N) x 128(K).
// A smem: [128 m][64 kpair] uint2 (hi,lo). B smem: [128 n][64 kpair] uint2.
#define KPS 66   // padded kpair stride per row
__global__ void __launch_bounds__(256, 1)
qkv_gemm_mma(const float* __restrict__ embeds,
             const float* __restrict__ qT,
             const float* __restrict__ kT,
             const float* __restrict__ vT,
             int N) {
    extern __shared__ uint2 smem[];
    uint2* As = smem;                 // 128 * KPS
    uint2* Bs = smem + 128 * KPS;     // 128 * KPS

    const int tid = threadIdx.x;
    const int wid = tid >> 5;
    const int lane = tid & 31;
    const int m0 = blockIdx.x * 128;

    const int wm = wid & 3;           // 0..3  -> m base wm*32
    const int wn = wid >> 2;          // 0..1  -> n base wn*64
    const int r = lane >> 2;          // 0..7
    const int c = lane & 3;           // 0..3

    // ---- A: load + split once ----
    for (int t = tid; t < 128 * 32; t += 256) {
        int m = t >> 5;
        int f4 = t & 31;
        float4 v = make_float4(0.f, 0.f, 0.f, 0.f);
        if (m0 + m < N) v = ((const float4*)embeds)[(size_t)(m0 + m) * 32 + f4];
        As[m * KPS + 2 * f4]     = split2(v.x, v.y);
        As[m * KPS + 2 * f4 + 1] = split2(v.z, v.w);
    }

    const float* Wsrc[3] = {qT, kT, vT};
    float* Dsrc[3] = {g_Q, g_K, g_V};

    for (int w = 0; w < 3; ++w) {
        __syncthreads();   // previous compute done reading Bs
        // ---- B: transpose + split W[k][n] -> Bs[n][kpair] ----
        const float* W = Wsrc[w];
        for (int t = tid; t < 64 * 128; t += 256) {
            int kp = t >> 7;       // 0..63
            int n = t & 127;       // consecutive lanes -> consecutive n (coalesced)
            float w0 = W[(2 * kp) * 128 + n];
            float w1 = W[(2 * kp + 1) * 128 + n];
            Bs[n * KPS + kp] = split2(w0, w1);
        }
        __syncthreads();

        float acc[2][8][4];
#pragma unroll
        for (int mt = 0; mt < 2; ++mt)
#pragma unroll
            for (int nt = 0; nt < 8; ++nt)
#pragma unroll
                for (int i = 0; i < 4; ++i) acc[mt][nt][i] = 0.0f;

#pragma unroll
        for (int s = 0; s < 8; ++s) {
            const int kp0 = s * 8 + c;

            uint32_t ah[2][4], al[2][4];
#pragma unroll
            for (int mt = 0; mt < 2; ++mt) {
                const uint2* base = As + (wm * 32 + mt * 16 + r) * KPS;
                uint2 p00 = base[kp0];               // a0: row r,   kp c
                uint2 p10 = base[8 * KPS + kp0];     // a1: row r+8, kp c
                uint2 p01 = base[kp0 + 4];           // a2: row r,   kp c+4
                uint2 p11 = base[8 * KPS + kp0 + 4]; // a3: row r+8, kp c+4
                ah[mt][0] = p00.x; ah[mt][1] = p10.x; ah[mt][2] = p01.x; ah[mt][3] = p11.x;
                al[mt][0] = p00.y; al[mt][1] = p10.y; al[mt][2] = p01.y; al[mt][3] = p11.y;
            }

#pragma unroll
            for (int nt = 0; nt < 8; ++nt) {
                const uint2* nb = Bs + (wn * 64 + nt * 8 + r) * KPS;
                uint2 q0 = nb[kp0];       // b0: kp c
                uint2 q1 = nb[kp0 + 4];   // b1: kp c+4
#pragma unroll
                for (int mt = 0; mt < 2; ++mt) {
                    mma_bf16(acc[mt][nt], ah[mt], q0.x, q1.x);  // Ah*Bh
                    mma_bf16(acc[mt][nt], ah[mt], q0.y, q1.y);  // Ah*Bl
                    mma_bf16(acc[mt][nt], al[mt], q0.x, q1.x);  // Al*Bh
                }
            }
        }

        // ---- epilogue ----
        float* D = Dsrc[w];
#pragma unroll
        for (int mt = 0; mt < 2; ++mt) {
            int grow = m0 + wm * 32 + mt * 16 + r;
#pragma unroll
            for (int nt = 0; nt < 8; ++nt) {
                int gcol = wn * 64 + nt * 8 + c * 2;
                if (grow < N) {
                    float2 v0 = make_float2(acc[mt][nt][0], acc[mt][nt][1]);
                    *(float2*)&D[(size_t)grow * 128 + gcol] = v0;
                }
                if (grow + 8 < N) {
                    float2 v1 = make_float2(acc[mt][nt][2], acc[mt][nt][3]);
                    *(float2*)&D[(size_t)(grow + 8) * 128 + gcol] = v1;
                }
            }
        }
    }
}

// ---------------- Edge pass A: 2 edges per warp ----------------
__global__ void __launch_bounds__(256)
edge_att(const int* __restrict__ rows, const int* __restrict__ cols,
         const float* __restrict__ filt, int E) {
    int w = (blockIdx.x * blockDim.x + threadIdx.x) >> 5;
    int lane = threadIdx.x & 31;
    int e0 = 2 * w;
    if (e0 >= E) return;
    bool has1 = (e0 + 1 < E);

    int r0 = __ldg(&rows[e0]);
    int c0 = __ldg(&cols[e0]);
    int r1 = has1 ? __ldg(&rows[e0 + 1]) : r0;
    int c1 = has1 ? __ldg(&cols[e0 + 1]) : c0;

    float4 q0 = ((const float4*)g_Q)[(size_t)r0 * 32 + lane];
    float4 k0 = ((const float4*)g_K)[(size_t)c0 * 32 + lane];
    float4 q1 = ((const float4*)g_Q)[(size_t)r1 * 32 + lane];
    float4 k1 = ((const float4*)g_K)[(size_t)c1 * 32 + lane];

    float p0 = q0.x * k0.x + q0.y * k0.y + q0.z * k0.z + q0.w * k0.w;
    float p1 = q1.x * k1.x + q1.y * k1.y + q1.z * k1.z + q1.w * k1.w;
#pragma unroll
    for (int off = 4; off >= 1; off >>= 1) {
        p0 += __shfl_xor_sync(0xffffffffu, p0, off);
        p1 += __shfl_xor_sync(0xffffffffu, p1, off);
    }

    if ((lane & 7) == 0) {
        int h = lane >> 3;
        float f0 = __ldg(&filt[(size_t)c0 * 4 + h]);
        float att0 = fminf(fmaxf(p0, -10.0f), 10.0f) + f0;
        float ea0 = expf(att0);
        g_expAtt[(size_t)e0 * 4 + h] = ea0;
        atomicAdd(&g_attNorm[(size_t)r0 * 4 + h], ea0);
        if (has1) {
            float f1 = __ldg(&filt[(size_t)c1 * 4 + h]);
            float att1 = fminf(fmaxf(p1, -10.0f), 10.0f) + f1;
            float ea1 = expf(att1);
            g_expAtt[(size_t)(e0 + 1) * 4 + h] = ea1;
            atomicAdd(&g_attNorm[(size_t)r1 * 4 + h], ea1);
        }
    }
}

// ---------------- Edge pass B: 2 edges per warp, weighted V scatter ----------------
__global__ void __launch_bounds__(256)
edge_agg(const int* __restrict__ rows, const int* __restrict__ cols,
         float* __restrict__ out, int E) {
    int w = (blockIdx.x * blockDim.x + threadIdx.x) >> 5;
    int lane = threadIdx.x & 31;
    int e0 = 2 * w;
    if (e0 >= E) return;
    bool has1 = (e0 + 1 < E);
    int h = lane >> 3;

    int r0 = __ldg(&rows[e0]);
    int c0 = __ldg(&cols[e0]);
    int r1 = has1 ? __ldg(&rows[e0 + 1]) : r0;
    int c1 = has1 ? __ldg(&cols[e0 + 1]) : c0;

    float ea0 = __ldg(&g_expAtt[(size_t)e0 * 4 + h]);
    float nm0 = __ldg(&g_attNorm[(size_t)r0 * 4 + h]);
    float ea1 = __ldg(&g_expAtt[(size_t)(e0 + (has1 ? 1 : 0)) * 4 + h]);
    float nm1 = __ldg(&g_attNorm[(size_t)r1 * 4 + h]);
    float4 v0 = ((const float4*)g_V)[(size_t)c0 * 32 + lane];
    float4 v1 = ((const float4*)g_V)[(size_t)c1 * 32 + lane];

    float w0 = ea0 / (nm0 + 1e-8f);
    v0.x *= w0; v0.y *= w0; v0.z *= w0; v0.w *= w0;
    float* dst0 = out + (size_t)r0 * 128 + lane * 4;
    asm volatile("red.global.add.v4.f32 [%0], {%1, %2, %3, %4};"
                 :: "l"(dst0), "f"(v0.x), "f"(v0.y), "f"(v0.z), "f"(v0.w)
                 : "memory");

    if (has1) {
        float w1 = ea1 / (nm1 + 1e-8f);
        v1.x *= w1; v1.y *= w1; v1.z *= w1; v1.w *= w1;
        float* dst1 = out + (size_t)r1 * 128 + lane * 4;
        asm volatile("red.global.add.v4.f32 [%0], {%1, %2, %3, %4};"
                     :: "l"(dst1), "f"(v1.x), "f"(v1.y), "f"(v1.z), "f"(v1.w)
                     : "memory");
    }
}

// ---------------- launch ----------------
extern "C" void kernel_launch(void* const* d_in, const int* in_sizes, int n_in,
                              void* d_out, int out_size) {
    const float* embeds = (const float*)d_in[0];
    const float* qT = (const float*)d_in[1];
    const float* kT = (const float*)d_in[2];
    const float* vT = (const float*)d_in[3];
    const float* filt = (const float*)d_in[4];
    const int* rows = (const int*)d_in[5];
    const int* cols = (const int*)d_in[6];
    float* out = (float*)d_out;

    int N = in_sizes[0] / LATDIM;
    int E = in_sizes[5];

    static const int GEMM_SMEM = 2 * 128 * KPS * (int)sizeof(uint2);  // 135168 B
    cudaFuncSetAttribute(qkv_gemm_mma, cudaFuncAttributeMaxDynamicSharedMemorySize, GEMM_SMEM);

    zero_kernel<<<1024, 256>>>(out, N * LATDIM, N * HEADS);
    qkv_gemm_mma<<<(N + 127) / 128, 256, GEMM_SMEM>>>(embeds, qT, kT, vT, N);

    int nWarps = (E + 1) / 2;
    int blocksE = (nWarps * 32 + 255) / 256;
    edge_att<<<blocksE, 256>>>(rows, cols, filt, E);
    edge_agg<<<blocksE, 256>>>(rows, cols, out, E);
}

// round 6
// speedup vs baseline: 1.3423x; 1.0153x over previous
#include <cuda_runtime.h>
#include <cuda_bf16.h>
#include <cstdint>

#define LATDIM 128
#define HEADS 4
#define MAXN 100000
#define MAXE 600000

// Scratch (allocation-free: device globals)
__device__ float g_Q[(size_t)MAXN * LATDIM];
__device__ float g_K[(size_t)MAXN * LATDIM];
__device__ float g_V[(size_t)MAXN * LATDIM];
__device__ float g_expAtt[(size_t)MAXE * HEADS];
__device__ float g_attNorm[(size_t)MAXN * HEADS];

// ---------------- zero out + attNorm ----------------
__global__ void zero_kernel(float* __restrict__ out, int n_out, int n_norm) {
    int stride = gridDim.x * blockDim.x;
    int i0 = blockIdx.x * blockDim.x + threadIdx.x;
    for (int i = i0; i < n_out; i += stride) out[i] = 0.0f;
    for (int i = i0; i < n_norm; i += stride) g_attNorm[i] = 0.0f;
}

// ---------------- bf16 split helpers ----------------
__device__ __forceinline__ uint2 split2(float x0, float x1) {
    __nv_bfloat16 h0 = __float2bfloat16(x0);
    __nv_bfloat16 h1 = __float2bfloat16(x1);
    __nv_bfloat16 l0 = __float2bfloat16(x0 - __bfloat162float(h0));
    __nv_bfloat16 l1 = __float2bfloat16(x1 - __bfloat162float(h1));
    __nv_bfloat162 hh = __nv_bfloat162(h0, h1);
    __nv_bfloat162 ll = __nv_bfloat162(l0, l1);
    uint2 r;
    r.x = *reinterpret_cast<uint32_t*>(&hh);
    r.y = *reinterpret_cast<uint32_t*>(&ll);
    return r;
}

__device__ __forceinline__ void mma_bf16(float* d, const uint32_t* a,
                                         uint32_t b0, uint32_t b1) {
    asm volatile(
        "mma.sync.aligned.m16n8k16.row.col.f32.bf16.bf16.f32 "
        "{%0,%1,%2,%3}, {%4,%5,%6,%7}, {%8,%9}, {%0,%1,%2,%3};"
        : "+f"(d[0]), "+f"(d[1]), "+f"(d[2]), "+f"(d[3])
        : "r"(a[0]), "r"(a[1]), "r"(a[2]), "r"(a[3]), "r"(b0), "r"(b1));
}

// ---------------- QKV GEMM on tensor cores (mma.sync bf16, 3-term split) ----------------
// CTA: 256 threads = 8 warps (4 M x 2 N). CTA tile 128(M) x 128(N) x 128(K).
#define KPS 66
__global__ void __launch_bounds__(256, 1)
qkv_gemm_mma(const float* __restrict__ embeds,
             const float* __restrict__ qT,
             const float* __restrict__ kT,
             const float* __restrict__ vT,
             int N) {
    extern __shared__ uint2 smem[];
    uint2* As = smem;                 // 128 * KPS
    uint2* Bs = smem + 128 * KPS;     // 128 * KPS

    const int tid = threadIdx.x;
    const int wid = tid >> 5;
    const int lane = tid & 31;
    const int m0 = blockIdx.x * 128;

    const int wm = wid & 3;
    const int wn = wid >> 2;
    const int r = lane >> 2;
    const int c = lane & 3;

    // ---- A: load + split once ----
    for (int t = tid; t < 128 * 32; t += 256) {
        int m = t >> 5;
        int f4 = t & 31;
        float4 v = make_float4(0.f, 0.f, 0.f, 0.f);
        if (m0 + m < N) v = ((const float4*)embeds)[(size_t)(m0 + m) * 32 + f4];
        As[m * KPS + 2 * f4]     = split2(v.x, v.y);
        As[m * KPS + 2 * f4 + 1] = split2(v.z, v.w);
    }

    const float* Wsrc[3] = {qT, kT, vT};
    float* Dsrc[3] = {g_Q, g_K, g_V};

    for (int w = 0; w < 3; ++w) {
        __syncthreads();
        const float* W = Wsrc[w];
        for (int t = tid; t < 64 * 128; t += 256) {
            int kp = t >> 7;
            int n = t & 127;
            float w0 = W[(2 * kp) * 128 + n];
            float w1 = W[(2 * kp + 1) * 128 + n];
            Bs[n * KPS + kp] = split2(w0, w1);
        }
        __syncthreads();

        float acc[2][8][4];
#pragma unroll
        for (int mt = 0; mt < 2; ++mt)
#pragma unroll
            for (int nt = 0; nt < 8; ++nt)
#pragma unroll
                for (int i = 0; i < 4; ++i) acc[mt][nt][i] = 0.0f;

#pragma unroll
        for (int s = 0; s < 8; ++s) {
            const int kp0 = s * 8 + c;

            uint32_t ah[2][4], al[2][4];
#pragma unroll
            for (int mt = 0; mt < 2; ++mt) {
                const uint2* base = As + (wm * 32 + mt * 16 + r) * KPS;
                uint2 p00 = base[kp0];
                uint2 p10 = base[8 * KPS + kp0];
                uint2 p01 = base[kp0 + 4];
                uint2 p11 = base[8 * KPS + kp0 + 4];
                ah[mt][0] = p00.x; ah[mt][1] = p10.x; ah[mt][2] = p01.x; ah[mt][3] = p11.x;
                al[mt][0] = p00.y; al[mt][1] = p10.y; al[mt][2] = p01.y; al[mt][3] = p11.y;
            }

            // Load ALL B fragments for this k-step first (bursts LDS, frees deps)
            uint32_t bh[8][2], bl[8][2];
#pragma unroll
            for (int nt = 0; nt < 8; ++nt) {
                const uint2* nb = Bs + (wn * 64 + nt * 8 + r) * KPS;
                uint2 q0 = nb[kp0];
                uint2 q1 = nb[kp0 + 4];
                bh[nt][0] = q0.x; bh[nt][1] = q1.x;
                bl[nt][0] = q0.y; bl[nt][1] = q1.y;
            }

            // Term-major issue: 16 independent MMAs between reuses of any acc
#pragma unroll
            for (int nt = 0; nt < 8; ++nt)
#pragma unroll
                for (int mt = 0; mt < 2; ++mt)
                    mma_bf16(acc[mt][nt], ah[mt], bh[nt][0], bh[nt][1]);   // Ah*Bh
#pragma unroll
            for (int nt = 0; nt < 8; ++nt)
#pragma unroll
                for (int mt = 0; mt < 2; ++mt)
                    mma_bf16(acc[mt][nt], ah[mt], bl[nt][0], bl[nt][1]);   // Ah*Bl
#pragma unroll
            for (int nt = 0; nt < 8; ++nt)
#pragma unroll
                for (int mt = 0; mt < 2; ++mt)
                    mma_bf16(acc[mt][nt], al[mt], bh[nt][0], bh[nt][1]);   // Al*Bh
        }

        // ---- epilogue ----
        float* D = Dsrc[w];
#pragma unroll
        for (int mt = 0; mt < 2; ++mt) {
            int grow = m0 + wm * 32 + mt * 16 + r;
#pragma unroll
            for (int nt = 0; nt < 8; ++nt) {
                int gcol = wn * 64 + nt * 8 + c * 2;
                if (grow < N) {
                    float2 v0 = make_float2(acc[mt][nt][0], acc[mt][nt][1]);
                    *(float2*)&D[(size_t)grow * 128 + gcol] = v0;
                }
                if (grow + 8 < N) {
                    float2 v1 = make_float2(acc[mt][nt][2], acc[mt][nt][3]);
                    *(float2*)&D[(size_t)(grow + 8) * 128 + gcol] = v1;
                }
            }
        }
    }
}

// ---------------- Edge pass A: 4 edges per warp ----------------
__global__ void __launch_bounds__(256)
edge_att(const int* __restrict__ rows, const int* __restrict__ cols,
         const float* __restrict__ filt, int E) {
    int w = (blockIdx.x * blockDim.x + threadIdx.x) >> 5;
    int lane = threadIdx.x & 31;
    int e0 = 4 * w;
    if (e0 >= E) return;
    int ecnt = min(4, E - e0);

    int rr[4], cc[4];
#pragma unroll
    for (int u = 0; u < 4; ++u) {
        int e = e0 + ((u < ecnt) ? u : 0);
        rr[u] = __ldg(&rows[e]);
        cc[u] = __ldg(&cols[e]);
    }

    float4 q[4], k[4];
#pragma unroll
    for (int u = 0; u < 4; ++u) {
        q[u] = ((const float4*)g_Q)[(size_t)rr[u] * 32 + lane];
        k[u] = ((const float4*)g_K)[(size_t)cc[u] * 32 + lane];
    }

    float p[4];
#pragma unroll
    for (int u = 0; u < 4; ++u)
        p[u] = q[u].x * k[u].x + q[u].y * k[u].y + q[u].z * k[u].z + q[u].w * k[u].w;

#pragma unroll
    for (int off = 4; off >= 1; off >>= 1)
#pragma unroll
        for (int u = 0; u < 4; ++u)
            p[u] += __shfl_xor_sync(0xffffffffu, p[u], off);

    if ((lane & 7) == 0) {
        int h = lane >> 3;
#pragma unroll
        for (int u = 0; u < 4; ++u) {
            if (u < ecnt) {
                float f = __ldg(&filt[(size_t)cc[u] * 4 + h]);
                float att = fminf(fmaxf(p[u], -10.0f), 10.0f) + f;
                float ea = expf(att);
                g_expAtt[(size_t)(e0 + u) * 4 + h] = ea;
                atomicAdd(&g_attNorm[(size_t)rr[u] * 4 + h], ea);
            }
        }
    }
}

// ---------------- Edge pass B: 4 edges per warp, weighted V scatter ----------------
__global__ void __launch_bounds__(256)
edge_agg(const int* __restrict__ rows, const int* __restrict__ cols,
         float* __restrict__ out, int E) {
    int w = (blockIdx.x * blockDim.x + threadIdx.x) >> 5;
    int lane = threadIdx.x & 31;
    int e0 = 4 * w;
    if (e0 >= E) return;
    int ecnt = min(4, E - e0);
    int h = lane >> 3;

    int rr[4], cc[4];
#pragma unroll
    for (int u = 0; u < 4; ++u) {
        int e = e0 + ((u < ecnt) ? u : 0);
        rr[u] = __ldg(&rows[e]);
        cc[u] = __ldg(&cols[e]);
    }

    float ea[4], nm[4];
    float4 v[4];
#pragma unroll
    for (int u = 0; u < 4; ++u) {
        int e = e0 + ((u < ecnt) ? u : 0);
        ea[u] = __ldg(&g_expAtt[(size_t)e * 4 + h]);
        nm[u] = __ldg(&g_attNorm[(size_t)rr[u] * 4 + h]);
        v[u] = ((const float4*)g_V)[(size_t)cc[u] * 32 + lane];
    }

#pragma unroll
    for (int u = 0; u < 4; ++u) {
        if (u < ecnt) {
            float wgt = ea[u] / (nm[u] + 1e-8f);
            float4 s = v[u];
            s.x *= wgt; s.y *= wgt; s.z *= wgt; s.w *= wgt;
            float* dst = out + (size_t)rr[u] * 128 + lane * 4;
            asm volatile("red.global.add.v4.f32 [%0], {%1, %2, %3, %4};"
                         :: "l"(dst), "f"(s.x), "f"(s.y), "f"(s.z), "f"(s.w)
                         : "memory");
        }
    }
}

// ---------------- launch ----------------
extern "C" void kernel_launch(void* const* d_in, const int* in_sizes, int n_in,
                              void* d_out, int out_size) {
    const float* embeds = (const float*)d_in[0];
    const float* qT = (const float*)d_in[1];
    const float* kT = (const float*)d_in[2];
    const float* vT = (const float*)d_in[3];
    const float* filt = (const float*)d_in[4];
    const int* rows = (const int*)d_in[5];
    const int* cols = (const int*)d_in[6];
    float* out = (float*)d_out;

    int N = in_sizes[0] / LATDIM;
    int E = in_sizes[5];

    static const int GEMM_SMEM = 2 * 128 * KPS * (int)sizeof(uint2);
    cudaFuncSetAttribute(qkv_gemm_mma, cudaFuncAttributeMaxDynamicSharedMemorySize, GEMM_SMEM);

    zero_kernel<<<1024, 256>>>(out, N * LATDIM, N * HEADS);
    qkv_gemm_mma<<<(N + 127) / 128, 256, GEMM_SMEM>>>(embeds, qT, kT, vT, N);

    int nWarps = (E + 3) / 4;
    int blocksE = (nWarps * 32 + 255) / 256;
    edge_att<<<blocksE, 256>>>(rows, cols, filt, E);
    edge_agg<<<blocksE, 256>>>(rows, cols, out, E);
}

// round 7
// speedup vs baseline: 1.6348x; 1.2179x over previous
#include <cuda_runtime.h>
#include <cuda_bf16.h>
#include <cstdint>

#define LATDIM 128
#define HEADS 4
#define MAXN 100000
#define MAXE 600000

// Scratch (allocation-free: device globals)
__device__ float g_Q[(size_t)MAXN * LATDIM];
__device__ float g_K[(size_t)MAXN * LATDIM];
__device__ float g_V[(size_t)MAXN * LATDIM];
__device__ float g_attNorm[(size_t)MAXN * HEADS];
#define KPS 66
__device__ uint2 g_Bs[3][128 * KPS];   // pre-split weights (hi,lo bf16x2 pairs)

// ---------------- bf16 split helpers ----------------
__device__ __forceinline__ uint2 split2(float x0, float x1) {
    __nv_bfloat16 h0 = __float2bfloat16(x0);
    __nv_bfloat16 h1 = __float2bfloat16(x1);
    __nv_bfloat16 l0 = __float2bfloat16(x0 - __bfloat162float(h0));
    __nv_bfloat16 l1 = __float2bfloat16(x1 - __bfloat162float(h1));
    __nv_bfloat162 hh = __nv_bfloat162(h0, h1);
    __nv_bfloat162 ll = __nv_bfloat162(l0, l1);
    uint2 r;
    r.x = *reinterpret_cast<uint32_t*>(&hh);
    r.y = *reinterpret_cast<uint32_t*>(&ll);
    return r;
}

__device__ __forceinline__ void mma_bf16(float* d, const uint32_t* a,
                                         uint32_t b0, uint32_t b1) {
    asm volatile(
        "mma.sync.aligned.m16n8k16.row.col.f32.bf16.bf16.f32 "
        "{%0,%1,%2,%3}, {%4,%5,%6,%7}, {%8,%9}, {%0,%1,%2,%3};"
        : "+f"(d[0]), "+f"(d[1]), "+f"(d[2]), "+f"(d[3])
        : "r"(a[0]), "r"(a[1]), "r"(a[2]), "r"(a[3]), "r"(b0), "r"(b1));
}

// ---------------- zero kernels (split so gemm is launch #4) ----------------
__global__ void zero_out1(float* __restrict__ out, int n_half) {
    int stride = gridDim.x * blockDim.x;
    for (int i = blockIdx.x * blockDim.x + threadIdx.x; i < n_half; i += stride)
        out[i] = 0.0f;
}
__global__ void zero_out2(float* __restrict__ out, int n_half, int n_out, int n_norm) {
    int stride = gridDim.x * blockDim.x;
    int i0 = blockIdx.x * blockDim.x + threadIdx.x;
    for (int i = n_half + i0; i < n_out; i += stride) out[i] = 0.0f;
    for (int i = i0; i < n_norm; i += stride) g_attNorm[i] = 0.0f;
}

// ---------------- pre-split weights: W[k][n] -> g_Bs[w][n*KPS+kp] ----------------
__global__ void presplit_b(const float* __restrict__ qT,
                           const float* __restrict__ kT,
                           const float* __restrict__ vT) {
    int t = blockIdx.x * blockDim.x + threadIdx.x;
    if (t >= 3 * 8192) return;
    int w = t / 8192;
    int i = t % 8192;
    int kp = i >> 7;       // 0..63
    int n = i & 127;
    const float* W = (w == 0) ? qT : (w == 1) ? kT : vT;
    float w0 = W[(2 * kp) * 128 + n];
    float w1 = W[(2 * kp + 1) * 128 + n];
    g_Bs[w][n * KPS + kp] = split2(w0, w1);
}

// ---------------- QKV GEMM on tensor cores (mma.sync bf16, 3-term split) ----------------
// CTA: 256 threads = 8 warps (4 M x 2 N). CTA tile 128(M) x 128(N) x 128(K).
__global__ void __launch_bounds__(256, 1)
qkv_gemm_mma(const float* __restrict__ embeds, int N) {
    extern __shared__ uint2 smem[];
    uint2* As = smem;                 // 128 * KPS
    uint2* Bs = smem + 128 * KPS;     // 128 * KPS

    const int tid = threadIdx.x;
    const int wid = tid >> 5;
    const int lane = tid & 31;
    const int m0 = blockIdx.x * 128;

    const int wm = wid & 3;
    const int wn = wid >> 2;
    const int r = lane >> 2;
    const int c = lane & 3;

    // ---- A: load + split once ----
    for (int t = tid; t < 128 * 32; t += 256) {
        int m = t >> 5;
        int f4 = t & 31;
        float4 v = make_float4(0.f, 0.f, 0.f, 0.f);
        if (m0 + m < N) v = ((const float4*)embeds)[(size_t)(m0 + m) * 32 + f4];
        As[m * KPS + 2 * f4]     = split2(v.x, v.y);
        As[m * KPS + 2 * f4 + 1] = split2(v.z, v.w);
    }

    float* Dsrc[3] = {g_Q, g_K, g_V};

    for (int w = 0; w < 3; ++w) {
        __syncthreads();
        // ---- B: straight copy of pre-split tile (128*KPS uint2 = 4224 uint4) ----
        {
            uint4* dst = (uint4*)Bs;
            const uint4* src = (const uint4*)g_Bs[w];
            for (int t = tid; t < 128 * KPS / 2; t += 256) dst[t] = src[t];
        }
        __syncthreads();

        float acc[2][8][4];
#pragma unroll
        for (int mt = 0; mt < 2; ++mt)
#pragma unroll
            for (int nt = 0; nt < 8; ++nt)
#pragma unroll
                for (int i = 0; i < 4; ++i) acc[mt][nt][i] = 0.0f;

#pragma unroll
        for (int s = 0; s < 8; ++s) {
            const int kp0 = s * 8 + c;

            uint32_t ah[2][4], al[2][4];
#pragma unroll
            for (int mt = 0; mt < 2; ++mt) {
                const uint2* base = As + (wm * 32 + mt * 16 + r) * KPS;
                uint2 p00 = base[kp0];
                uint2 p10 = base[8 * KPS + kp0];
                uint2 p01 = base[kp0 + 4];
                uint2 p11 = base[8 * KPS + kp0 + 4];
                ah[mt][0] = p00.x; ah[mt][1] = p10.x; ah[mt][2] = p01.x; ah[mt][3] = p11.x;
                al[mt][0] = p00.y; al[mt][1] = p10.y; al[mt][2] = p01.y; al[mt][3] = p11.y;
            }

            uint32_t bh[8][2], bl[8][2];
#pragma unroll
            for (int nt = 0; nt < 8; ++nt) {
                const uint2* nb = Bs + (wn * 64 + nt * 8 + r) * KPS;
                uint2 q0 = nb[kp0];
                uint2 q1 = nb[kp0 + 4];
                bh[nt][0] = q0.x; bh[nt][1] = q1.x;
                bl[nt][0] = q0.y; bl[nt][1] = q1.y;
            }

#pragma unroll
            for (int nt = 0; nt < 8; ++nt)
#pragma unroll
                for (int mt = 0; mt < 2; ++mt)
                    mma_bf16(acc[mt][nt], ah[mt], bh[nt][0], bh[nt][1]);
#pragma unroll
            for (int nt = 0; nt < 8; ++nt)
#pragma unroll
                for (int mt = 0; mt < 2; ++mt)
                    mma_bf16(acc[mt][nt], ah[mt], bl[nt][0], bl[nt][1]);
#pragma unroll
            for (int nt = 0; nt < 8; ++nt)
#pragma unroll
                for (int mt = 0; mt < 2; ++mt)
                    mma_bf16(acc[mt][nt], al[mt], bh[nt][0], bh[nt][1]);
        }

        // ---- epilogue ----
        float* D = Dsrc[w];
#pragma unroll
        for (int mt = 0; mt < 2; ++mt) {
            int grow = m0 + wm * 32 + mt * 16 + r;
#pragma unroll
            for (int nt = 0; nt < 8; ++nt) {
                int gcol = wn * 64 + nt * 8 + c * 2;
                if (grow < N) {
                    float2 v0 = make_float2(acc[mt][nt][0], acc[mt][nt][1]);
                    *(float2*)&D[(size_t)grow * 128 + gcol] = v0;
                }
                if (grow + 8 < N) {
                    float2 v1 = make_float2(acc[mt][nt][2], acc[mt][nt][3]);
                    *(float2*)&D[(size_t)(grow + 8) * 128 + gcol] = v1;
                }
            }
        }
    }
}

// ---------------- Fused edge pass: logits + exp + unnormalized scatter ----------------
// 2 edges per warp. out accumulates ea*V (RED.v4); attNorm accumulates ea.
__global__ void __launch_bounds__(256)
edge_fused(const int* __restrict__ rows, const int* __restrict__ cols,
           const float* __restrict__ filt, float* __restrict__ out, int E) {
    int w = (blockIdx.x * blockDim.x + threadIdx.x) >> 5;
    int lane = threadIdx.x & 31;
    int e0 = 2 * w;
    if (e0 >= E) return;
    bool has1 = (e0 + 1 < E);
    int h = lane >> 3;

    int r0 = __ldg(&rows[e0]);
    int c0 = __ldg(&cols[e0]);
    int r1 = has1 ? __ldg(&rows[e0 + 1]) : r0;
    int c1 = has1 ? __ldg(&cols[e0 + 1]) : c0;

    // 6 independent 16B gathers
    float4 q0 = ((const float4*)g_Q)[(size_t)r0 * 32 + lane];
    float4 k0 = ((const float4*)g_K)[(size_t)c0 * 32 + lane];
    float4 v0 = ((const float4*)g_V)[(size_t)c0 * 32 + lane];
    float4 q1 = ((const float4*)g_Q)[(size_t)r1 * 32 + lane];
    float4 k1 = ((const float4*)g_K)[(size_t)c1 * 32 + lane];
    float4 v1 = ((const float4*)g_V)[(size_t)c1 * 32 + lane];

    float p0 = q0.x * k0.x + q0.y * k0.y + q0.z * k0.z + q0.w * k0.w;
    float p1 = q1.x * k1.x + q1.y * k1.y + q1.z * k1.z + q1.w * k1.w;
#pragma unroll
    for (int off = 4; off >= 1; off >>= 1) {
        p0 += __shfl_xor_sync(0xffffffffu, p0, off);
        p1 += __shfl_xor_sync(0xffffffffu, p1, off);
    }

    float f0 = __ldg(&filt[(size_t)c0 * 4 + h]);
    float f1 = __ldg(&filt[(size_t)c1 * 4 + h]);
    float ea0 = expf(fminf(fmaxf(p0, -10.0f), 10.0f) + f0);
    float ea1 = expf(fminf(fmaxf(p1, -10.0f), 10.0f) + f1);

    v0.x *= ea0; v0.y *= ea0; v0.z *= ea0; v0.w *= ea0;
    float* dst0 = out + (size_t)r0 * 128 + lane * 4;
    asm volatile("red.global.add.v4.f32 [%0], {%1, %2, %3, %4};"
                 :: "l"(dst0), "f"(v0.x), "f"(v0.y), "f"(v0.z), "f"(v0.w)
                 : "memory");
    if (has1) {
        v1.x *= ea1; v1.y *= ea1; v1.z *= ea1; v1.w *= ea1;
        float* dst1 = out + (size_t)r1 * 128 + lane * 4;
        asm volatile("red.global.add.v4.f32 [%0], {%1, %2, %3, %4};"
                     :: "l"(dst1), "f"(v1.x), "f"(v1.y), "f"(v1.z), "f"(v1.w)
                     : "memory");
    }

    if ((lane & 7) == 0) {
        atomicAdd(&g_attNorm[(size_t)r0 * 4 + h], ea0);
        if (has1) atomicAdd(&g_attNorm[(size_t)r1 * 4 + h], ea1);
    }
}

// ---------------- normalize: out[r] /= (norm[r,h] + 1e-8) ----------------
__global__ void normalize_out(float* __restrict__ out, int N) {
    int i = blockIdx.x * blockDim.x + threadIdx.x;   // over N*32 float4s
    if (i >= N * 32) return;
    int r = i >> 5;
    int h = (i & 31) >> 3;
    float inv = 1.0f / (__ldg(&g_attNorm[(size_t)r * 4 + h]) + 1e-8f);
    float4 v = ((float4*)out)[i];
    v.x *= inv; v.y *= inv; v.z *= inv; v.w *= inv;
    ((float4*)out)[i] = v;
}

// ---------------- launch ----------------
extern "C" void kernel_launch(void* const* d_in, const int* in_sizes, int n_in,
                              void* d_out, int out_size) {
    const float* embeds = (const float*)d_in[0];
    const float* qT = (const float*)d_in[1];
    const float* kT = (const float*)d_in[2];
    const float* vT = (const float*)d_in[3];
    const float* filt = (const float*)d_in[4];
    const int* rows = (const int*)d_in[5];
    const int* cols = (const int*)d_in[6];
    float* out = (float*)d_out;

    int N = in_sizes[0] / LATDIM;
    int E = in_sizes[5];
    int n_out = N * LATDIM;
    int n_half = (n_out / 2) & ~3;

    static const int GEMM_SMEM = 2 * 128 * KPS * (int)sizeof(uint2);
    cudaFuncSetAttribute(qkv_gemm_mma, cudaFuncAttributeMaxDynamicSharedMemorySize, GEMM_SMEM);

    // Launch order chosen so the GEMM is the 4th launch (ncu profiles #4).
    zero_out1<<<1024, 256>>>(out, n_half);
    zero_out2<<<1024, 256>>>(out, n_half, n_out, N * HEADS);
    presplit_b<<<(3 * 8192 + 255) / 256, 256>>>(qT, kT, vT);
    qkv_gemm_mma<<<(N + 127) / 128, 256, GEMM_SMEM>>>(embeds, N);

    int nWarps = (E + 1) / 2;
    int blocksE = (nWarps * 32 + 255) / 256;
    edge_fused<<<blocksE, 256>>>(rows, cols, filt, out, E);
    normalize_out<<<(N * 32 + 255) / 256, 256>>>(out, N);
}

// round 8
// speedup vs baseline: 1.8776x; 1.1485x over previous
#include <cuda_runtime.h>
#include <cuda_bf16.h>
#include <cstdint>

#define LATDIM 128
#define HEADS 4
#define MAXN 100000
#define MAXE 600000

// Scratch (allocation-free: device globals)
__device__ float g_Q[(size_t)MAXN * LATDIM];
__device__ float g_K[(size_t)MAXN * LATDIM];
__device__ float g_V[(size_t)MAXN * LATDIM];
__device__ float g_attNorm[(size_t)MAXN * HEADS];
#define KPS 66
__device__ uint2 g_Bs[3][128 * KPS];   // pre-split weights (hi,lo bf16x2 pairs)

// ---------------- bf16 split helpers ----------------
__device__ __forceinline__ uint2 split2(float x0, float x1) {
    __nv_bfloat16 h0 = __float2bfloat16(x0);
    __nv_bfloat16 h1 = __float2bfloat16(x1);
    __nv_bfloat16 l0 = __float2bfloat16(x0 - __bfloat162float(h0));
    __nv_bfloat16 l1 = __float2bfloat16(x1 - __bfloat162float(h1));
    __nv_bfloat162 hh = __nv_bfloat162(h0, h1);
    __nv_bfloat162 ll = __nv_bfloat162(l0, l1);
    uint2 r;
    r.x = *reinterpret_cast<uint32_t*>(&hh);
    r.y = *reinterpret_cast<uint32_t*>(&ll);
    return r;
}

__device__ __forceinline__ void mma_bf16(float* d, const uint32_t* a,
                                         uint32_t b0, uint32_t b1) {
    asm volatile(
        "mma.sync.aligned.m16n8k16.row.col.f32.bf16.bf16.f32 "
        "{%0,%1,%2,%3}, {%4,%5,%6,%7}, {%8,%9}, {%0,%1,%2,%3};"
        : "+f"(d[0]), "+f"(d[1]), "+f"(d[2]), "+f"(d[3])
        : "r"(a[0]), "r"(a[1]), "r"(a[2]), "r"(a[3]), "r"(b0), "r"(b1));
}

// ---------------- zero kernels (split so gemm is launch #4) ----------------
__global__ void zero_out1(float* __restrict__ out, int n_half) {
    int stride = gridDim.x * blockDim.x;
    for (int i = blockIdx.x * blockDim.x + threadIdx.x; i < n_half; i += stride)
        out[i] = 0.0f;
}
__global__ void zero_out2(float* __restrict__ out, int n_half, int n_out, int n_norm) {
    int stride = gridDim.x * blockDim.x;
    int i0 = blockIdx.x * blockDim.x + threadIdx.x;
    for (int i = n_half + i0; i < n_out; i += stride) out[i] = 0.0f;
    for (int i = i0; i < n_norm; i += stride) g_attNorm[i] = 0.0f;
}

// ---------------- pre-split weights: W[k][n] -> g_Bs[w][n*KPS+kp] ----------------
__global__ void presplit_b(const float* __restrict__ qT,
                           const float* __restrict__ kT,
                           const float* __restrict__ vT) {
    int t = blockIdx.x * blockDim.x + threadIdx.x;
    if (t >= 3 * 8192) return;
    int w = t / 8192;
    int i = t % 8192;
    int kp = i >> 7;       // 0..63
    int n = i & 127;
    const float* W = (w == 0) ? qT : (w == 1) ? kT : vT;
    float w0 = W[(2 * kp) * 128 + n];
    float w1 = W[(2 * kp + 1) * 128 + n];
    g_Bs[w][n * KPS + kp] = split2(w0, w1);
}

// ---------------- QKV GEMM on tensor cores (mma.sync bf16, 3-term split) ----------------
// CTA: 256 threads = 8 warps (2 M x 4 N). CTA tile 64(M) x 128(N) x 128(K).
// 2 CTAs/SM (smem 101.4 KB, regs <= 128).
__global__ void __launch_bounds__(256, 2)
qkv_gemm_mma(const float* __restrict__ embeds, int N) {
    extern __shared__ uint2 smem[];
    uint2* As = smem;                 // 64 * KPS
    uint2* Bs = smem + 64 * KPS;      // 128 * KPS

    const int tid = threadIdx.x;
    const int wid = tid >> 5;
    const int lane = tid & 31;
    const int m0 = blockIdx.x * 64;

    const int wm = wid & 1;           // 0..1 -> m base wm*32
    const int wn = wid >> 1;          // 0..3 -> n base wn*32
    const int r = lane >> 2;          // 0..7
    const int c = lane & 3;           // 0..3

    // ---- A: load + split once (64 rows) ----
    for (int t = tid; t < 64 * 32; t += 256) {
        int m = t >> 5;
        int f4 = t & 31;
        float4 v = make_float4(0.f, 0.f, 0.f, 0.f);
        if (m0 + m < N) v = ((const float4*)embeds)[(size_t)(m0 + m) * 32 + f4];
        As[m * KPS + 2 * f4]     = split2(v.x, v.y);
        As[m * KPS + 2 * f4 + 1] = split2(v.z, v.w);
    }

    float* Dsrc[3] = {g_Q, g_K, g_V};

    for (int w = 0; w < 3; ++w) {
        __syncthreads();
        // ---- B: straight copy of pre-split tile ----
        {
            uint4* dst = (uint4*)Bs;
            const uint4* src = (const uint4*)g_Bs[w];
            for (int t = tid; t < 128 * KPS / 2; t += 256) dst[t] = src[t];
        }
        __syncthreads();

        float acc[2][4][4];
#pragma unroll
        for (int mt = 0; mt < 2; ++mt)
#pragma unroll
            for (int nt = 0; nt < 4; ++nt)
#pragma unroll
                for (int i = 0; i < 4; ++i) acc[mt][nt][i] = 0.0f;

#pragma unroll
        for (int s = 0; s < 8; ++s) {
            const int kp0 = s * 8 + c;

            uint32_t ah[2][4], al[2][4];
#pragma unroll
            for (int mt = 0; mt < 2; ++mt) {
                const uint2* base = As + (wm * 32 + mt * 16 + r) * KPS;
                uint2 p00 = base[kp0];
                uint2 p10 = base[8 * KPS + kp0];
                uint2 p01 = base[kp0 + 4];
                uint2 p11 = base[8 * KPS + kp0 + 4];
                ah[mt][0] = p00.x; ah[mt][1] = p10.x; ah[mt][2] = p01.x; ah[mt][3] = p11.x;
                al[mt][0] = p00.y; al[mt][1] = p10.y; al[mt][2] = p01.y; al[mt][3] = p11.y;
            }

            uint32_t bh[4][2], bl[4][2];
#pragma unroll
            for (int nt = 0; nt < 4; ++nt) {
                const uint2* nb = Bs + (wn * 32 + nt * 8 + r) * KPS;
                uint2 q0 = nb[kp0];
                uint2 q1 = nb[kp0 + 4];
                bh[nt][0] = q0.x; bh[nt][1] = q1.x;
                bl[nt][0] = q0.y; bl[nt][1] = q1.y;
            }

            // Term-major: 8 independent MMAs between reuses of any acc
#pragma unroll
            for (int nt = 0; nt < 4; ++nt)
#pragma unroll
                for (int mt = 0; mt < 2; ++mt)
                    mma_bf16(acc[mt][nt], ah[mt], bh[nt][0], bh[nt][1]);
#pragma unroll
            for (int nt = 0; nt < 4; ++nt)
#pragma unroll
                for (int mt = 0; mt < 2; ++mt)
                    mma_bf16(acc[mt][nt], ah[mt], bl[nt][0], bl[nt][1]);
#pragma unroll
            for (int nt = 0; nt < 4; ++nt)
#pragma unroll
                for (int mt = 0; mt < 2; ++mt)
                    mma_bf16(acc[mt][nt], al[mt], bh[nt][0], bh[nt][1]);
        }

        // ---- epilogue ----
        float* D = Dsrc[w];
#pragma unroll
        for (int mt = 0; mt < 2; ++mt) {
            int grow = m0 + wm * 32 + mt * 16 + r;
#pragma unroll
            for (int nt = 0; nt < 4; ++nt) {
                int gcol = wn * 32 + nt * 8 + c * 2;
                if (grow < N) {
                    float2 v0 = make_float2(acc[mt][nt][0], acc[mt][nt][1]);
                    *(float2*)&D[(size_t)grow * 128 + gcol] = v0;
                }
                if (grow + 8 < N) {
                    float2 v1 = make_float2(acc[mt][nt][2], acc[mt][nt][3]);
                    *(float2*)&D[(size_t)(grow + 8) * 128 + gcol] = v1;
                }
            }
        }
    }
}

// ---------------- Fused edge pass: logits + exp + unnormalized scatter ----------------
__global__ void __launch_bounds__(256)
edge_fused(const int* __restrict__ rows, const int* __restrict__ cols,
           const float* __restrict__ filt, float* __restrict__ out, int E) {
    int w = (blockIdx.x * blockDim.x + threadIdx.x) >> 5;
    int lane = threadIdx.x & 31;
    int e0 = 2 * w;
    if (e0 >= E) return;
    bool has1 = (e0 + 1 < E);
    int h = lane >> 3;

    int r0 = __ldg(&rows[e0]);
    int c0 = __ldg(&cols[e0]);
    int r1 = has1 ? __ldg(&rows[e0 + 1]) : r0;
    int c1 = has1 ? __ldg(&cols[e0 + 1]) : c0;

    float4 q0 = ((const float4*)g_Q)[(size_t)r0 * 32 + lane];
    float4 k0 = ((const float4*)g_K)[(size_t)c0 * 32 + lane];
    float4 v0 = ((const float4*)g_V)[(size_t)c0 * 32 + lane];
    float4 q1 = ((const float4*)g_Q)[(size_t)r1 * 32 + lane];
    float4 k1 = ((const float4*)g_K)[(size_t)c1 * 32 + lane];
    float4 v1 = ((const float4*)g_V)[(size_t)c1 * 32 + lane];

    float p0 = q0.x * k0.x + q0.y * k0.y + q0.z * k0.z + q0.w * k0.w;
    float p1 = q1.x * k1.x + q1.y * k1.y + q1.z * k1.z + q1.w * k1.w;
#pragma unroll
    for (int off = 4; off >= 1; off >>= 1) {
        p0 += __shfl_xor_sync(0xffffffffu, p0, off);
        p1 += __shfl_xor_sync(0xffffffffu, p1, off);
    }

    float f0 = __ldg(&filt[(size_t)c0 * 4 + h]);
    float f1 = __ldg(&filt[(size_t)c1 * 4 + h]);
    float ea0 = expf(fminf(fmaxf(p0, -10.0f), 10.0f) + f0);
    float ea1 = expf(fminf(fmaxf(p1, -10.0f), 10.0f) + f1);

    v0.x *= ea0; v0.y *= ea0; v0.z *= ea0; v0.w *= ea0;
    float* dst0 = out + (size_t)r0 * 128 + lane * 4;
    asm volatile("red.global.add.v4.f32 [%0], {%1, %2, %3, %4};"
                 :: "l"(dst0), "f"(v0.x), "f"(v0.y), "f"(v0.z), "f"(v0.w)
                 : "memory");
    if (has1) {
        v1.x *= ea1; v1.y *= ea1; v1.z *= ea1; v1.w *= ea1;
        float* dst1 = out + (size_t)r1 * 128 + lane * 4;
        asm volatile("red.global.add.v4.f32 [%0], {%1, %2, %3, %4};"
                     :: "l"(dst1), "f"(v1.x), "f"(v1.y), "f"(v1.z), "f"(v1.w)
                     : "memory");
    }

    if ((lane & 7) == 0) {
        atomicAdd(&g_attNorm[(size_t)r0 * 4 + h], ea0);
        if (has1) atomicAdd(&g_attNorm[(size_t)r1 * 4 + h], ea1);
    }
}

// ---------------- normalize: out[r] /= (norm[r,h] + 1e-8) ----------------
__global__ void normalize_out(float* __restrict__ out, int N) {
    int i = blockIdx.x * blockDim.x + threadIdx.x;
    if (i >= N * 32) return;
    int r = i >> 5;
    int h = (i & 31) >> 3;
    float inv = 1.0f / (__ldg(&g_attNorm[(size_t)r * 4 + h]) + 1e-8f);
    float4 v = ((float4*)out)[i];
    v.x *= inv; v.y *= inv; v.z *= inv; v.w *= inv;
    ((float4*)out)[i] = v;
}

// ---------------- launch ----------------
extern "C" void kernel_launch(void* const* d_in, const int* in_sizes, int n_in,
                              void* d_out, int out_size) {
    const float* embeds = (const float*)d_in[0];
    const float* qT = (const float*)d_in[1];
    const float* kT = (const float*)d_in[2];
    const float* vT = (const float*)d_in[3];
    const float* filt = (const float*)d_in[4];
    const int* rows = (const int*)d_in[5];
    const int* cols = (const int*)d_in[6];
    float* out = (float*)d_out;

    int N = in_sizes[0] / LATDIM;
    int E = in_sizes[5];
    int n_out = N * LATDIM;
    int n_half = (n_out / 2) & ~3;

    static const int GEMM_SMEM = (64 + 128) * KPS * (int)sizeof(uint2);  // 101376
    cudaFuncSetAttribute(qkv_gemm_mma, cudaFuncAttributeMaxDynamicSharedMemorySize, GEMM_SMEM);

    // GEMM stays launch #4 for ncu verification of the occupancy theory.
    zero_out1<<<1024, 256>>>(out, n_half);
    zero_out2<<<1024, 256>>>(out, n_half, n_out, N * HEADS);
    presplit_b<<<(3 * 8192 + 255) / 256, 256>>>(qT, kT, vT);
    qkv_gemm_mma<<<(N + 63) / 64, 256, GEMM_SMEM>>>(embeds, N);

    int nWarps = (E + 1) / 2;
    int blocksE = (nWarps * 32 + 255) / 256;
    edge_fused<<<blocksE, 256>>>(rows, cols, filt, out, E);
    normalize_out<<<(N * 32 + 255) / 256, 256>>>(out, N);
}